// round 10
// baseline (speedup 1.0000x reference)
#include <cuda_runtime.h>
#include <cuda_fp16.h>
#include <cstdint>

#define MAXN 100000
#define MAXE 3200000
#define FIN  128
#define HDIM 64
#define SCAN_B 256

typedef unsigned long long ull;

// Scratch (device globals — no cudaMalloc allowed).
__device__ float   g_deg  [MAXN];
__device__ float   g_dinv [MAXN];
__device__ int     g_fillc[MAXN];
__device__ int     g_rowptr[MAXN + 1];
__device__ int     g_bsum [(MAXN + SCAN_B - 1) / SCAN_B + 1];
__device__ int     g_adj  [MAXE];
__device__ __half2 g_hsh [(size_t)MAXN * (HDIM / 2)];  // row-scaled messages (fp16)
__device__ float4  g_agg4[(size_t)MAXN * (HDIM / 4)];  // aggregation result (fp32)
__device__ int     g_is64;                             // edge-index dtype flag
__device__ int     g_scanctr;                          // grid barrier counter

// packed fp32x2 fma: acc = a*b + acc (per 32-bit half)
#define FFMA2(acc, a, b) \
    asm("fma.rn.f32x2 %0, %1, %2, %0;" : "+l"(acc) : "l"(a), "l"(b))
#define UNPACK2(lo, hi, v) \
    asm("mov.b64 {%0, %1}, %2;" : "=f"(lo), "=f"(hi) : "l"(v))
#define PACKDUP(out, x) \
    asm("mov.b64 %0, {%1, %1};" : "=l"(out) : "f"(x))

// ---------------------------------------------------------------------------
// 1) init + dtype probe. int64 data => first 64 words all in [0, MAXN)
// ---------------------------------------------------------------------------
__global__ void init_kernel(const void* __restrict__ ei, int N) {
    int i = blockIdx.x * blockDim.x + threadIdx.x;
    if (i < N) g_deg[i] = 1.0f;
    if (i == 0) {
        g_scanctr = 0;                       // reset grid barrier every replay
        const long long* p = (const long long*)ei;
        int is64 = 1;
        #pragma unroll 1
        for (int k = 0; k < 64; k++) {
            long long v = p[k];
            if (v < 0 || v >= MAXN) { is64 = 0; break; }
        }
        g_is64 = is64;
    }
}

// ---------------------------------------------------------------------------
// 2) degree histogram over dst (2 edges/thread, vector index loads)
// ---------------------------------------------------------------------------
__global__ void deg_scatter_kernel(const void* __restrict__ ei, int E) {
    int t = blockIdx.x * blockDim.x + threadIdx.x;
    int e = 2 * t;
    if (e >= E) return;
    bool two = (e + 1 < E);
    int d0, d1 = 0;
    if (g_is64) {
        const long long* p = (const long long*)ei + E;
        if (two && ((E & 1) == 0)) {
            longlong2 dv = ((const longlong2*)p)[t];
            d0 = (int)dv.x; d1 = (int)dv.y;
        } else {
            d0 = (int)p[e];
            if (two) d1 = (int)p[e + 1];
        }
    } else {
        const int* p = (const int*)ei + E;
        if (two && ((E & 1) == 0)) {
            int2 dv = ((const int2*)p)[t];
            d0 = dv.x; d1 = dv.y;
        } else {
            d0 = p[e];
            if (two) d1 = p[e + 1];
        }
    }
    atomicAdd(&g_deg[d0], 1.0f);
    if (two) atomicAdd(&g_deg[d1], 1.0f);
}

// ---------------------------------------------------------------------------
// 3) single-kernel scan: local scan -> grid barrier -> cross-block prefix
// ---------------------------------------------------------------------------
__global__ void scan_kernel(int N, int E, int nblocks) {
    __shared__ int s[SCAN_B];
    __shared__ int blockPrefix;
    const int tid = threadIdx.x;
    const int i = blockIdx.x * SCAN_B + tid;

    float degv = (i < N) ? g_deg[i] : 1.0f;
    if (i < N) g_dinv[i] = rsqrtf(degv);
    int v = (i < N) ? (int)degv - 1 : 0;         // edge count into node i

    s[tid] = v;
    __syncthreads();
    #pragma unroll
    for (int off = 1; off < SCAN_B; off <<= 1) {
        int t = (tid >= off) ? s[tid - off] : 0;
        __syncthreads();
        s[tid] += t;
        __syncthreads();
    }
    const int incl = s[tid];                      // inclusive local scan
    if (tid == SCAN_B - 1) g_bsum[blockIdx.x] = incl;
    __threadfence();
    __syncthreads();

    // grid barrier (arrive-and-spin; all blocks co-resident)
    if (tid == 0) {
        atomicAdd(&g_scanctr, 1);
        while (atomicAdd(&g_scanctr, 0) < nblocks) { }
    }
    __syncthreads();
    __threadfence();

    // prefix of block sums before this block
    int p = 0;
    for (int b = tid; b < blockIdx.x; b += SCAN_B) p += g_bsum[b];
    __syncthreads();           // s[] reuse
    s[tid] = p;
    __syncthreads();
    #pragma unroll
    for (int off = SCAN_B / 2; off > 0; off >>= 1) {
        if (tid < off) s[tid] += s[tid + off];
        __syncthreads();
    }
    if (tid == 0) blockPrefix = s[0];
    __syncthreads();

    if (i < N) {
        int rp = blockPrefix + incl - v;          // exclusive global prefix
        g_rowptr[i] = rp;
        g_fillc[i]  = rp;
    }
    if (i == 0) g_rowptr[N] = E;
}

// ---------------------------------------------------------------------------
// 4) CSR fill (separate, zero smem -> full occupancy)
// ---------------------------------------------------------------------------
__global__ void fill_kernel(const void* __restrict__ ei, int E) {
    int t = blockIdx.x * blockDim.x + threadIdx.x;
    int e = 2 * t;
    if (e >= E) return;
    bool two = (e + 1 < E);
    int s0, s1 = 0, d0, d1 = 0;
    if (g_is64) {
        const long long* p = (const long long*)ei;
        if (two && ((E & 1) == 0)) {
            longlong2 sv = ((const longlong2*)p)[t];
            longlong2 dv = ((const longlong2*)(p + E))[t];
            s0 = (int)sv.x; s1 = (int)sv.y; d0 = (int)dv.x; d1 = (int)dv.y;
        } else {
            s0 = (int)p[e]; d0 = (int)p[E + e];
            if (two) { s1 = (int)p[e + 1]; d1 = (int)p[E + e + 1]; }
        }
    } else {
        const int* p = (const int*)ei;
        if (two && ((E & 1) == 0)) {
            int2 sv = ((const int2*)p)[t];
            int2 dv = ((const int2*)(p + E))[t];
            s0 = sv.x; s1 = sv.y; d0 = dv.x; d1 = dv.y;
        } else {
            s0 = p[e]; d0 = p[E + e];
            if (two) { s1 = p[e + 1]; d1 = p[E + e + 1]; }
        }
    }
    int pos0 = atomicAdd(&g_fillc[d0], 1);
    g_adj[pos0] = s0;
    if (two) {
        int pos1 = atomicAdd(&g_fillc[d1], 1);
        g_adj[pos1] = s1;
    }
}

// ---------------------------------------------------------------------------
// 5) transform1: hs = half((x @ W1) * dinv[row])  [f32x2 packed FMA]
//    x staged as duplicated pairs, two k-halves (smem cap 48KB).
// ---------------------------------------------------------------------------
__global__ void transform1_kernel(const float* __restrict__ x,
                                  const float* __restrict__ W1,
                                  int N) {
    __shared__ float Ws[FIN * HDIM];                       // 32 KB
    __shared__ __align__(16) ull xs[8][4][FIN / 2];        // 16 KB (dup pairs)
    const int tid = threadIdx.x;

    for (int i = tid; i < FIN * HDIM / 4; i += 256)
        ((float4*)Ws)[i] = ((const float4*)W1)[i];
    __syncthreads();

    const int w = tid >> 5, l = tid & 31;
    const int rowBase = blockIdx.x * 32 + w * 4;
    const ull* Wv = (const ull*)Ws;                        // [k*32 + l] = cols(2l,2l+1)

    ull acc[4] = {0ULL, 0ULL, 0ULL, 0ULL};

    #pragma unroll
    for (int half = 0; half < 2; half++) {
        const int kbase = half * (FIN / 2);
        #pragma unroll
        for (int r = 0; r < 4; r++) {
            int row = rowBase + r;
            float2 xv = {0.f, 0.f};
            if (row < N)
                xv = ((const float2*)(x + (size_t)row * FIN + kbase))[l];
            ull d0, d1;
            PACKDUP(d0, xv.x);
            PACKDUP(d1, xv.y);
            ((ulonglong2*)xs[w][r])[l] = make_ulonglong2(d0, d1);
        }
        __syncwarp();

        #pragma unroll 8
        for (int k2 = 0; k2 < FIN / 4; k2++) {             // 2 k per iter
            ull w0 = Wv[(kbase + 2 * k2)     * 32 + l];
            ull w1 = Wv[(kbase + 2 * k2 + 1) * 32 + l];
            #pragma unroll
            for (int r = 0; r < 4; r++) {
                ulonglong2 xr = ((const ulonglong2*)xs[w][r])[k2];
                FFMA2(acc[r], xr.x, w0);
                FFMA2(acc[r], xr.y, w1);
            }
        }
        __syncwarp();
    }

    #pragma unroll
    for (int r = 0; r < 4; r++) {
        int row = rowBase + r;
        if (row < N) {
            float d = g_dinv[row];
            float ax, ay;
            UNPACK2(ax, ay, acc[r]);
            g_hsh[(size_t)row * 32 + l] = __floats2half2_rn(ax * d, ay * d);
        }
    }
}

// ---------------------------------------------------------------------------
// 6) aggregation (gather): agg[i] = hs[i] + sum_{src in adj(i)} hs[src]
//    warp per node; lane = (slot 0..3, chunk 0..7); 4 neighbors per step.
// ---------------------------------------------------------------------------
__global__ void agg_kernel(int N) {
    int node = (blockIdx.x * blockDim.x + threadIdx.x) >> 5;
    if (node >= N) return;
    const int l     = threadIdx.x & 31;
    const int slot  = l >> 3;
    const int chunk = l & 7;
    const char* hbase = (const char*)g_hsh;
    const unsigned laneoff = chunk * 16;

    float2 a0 = {0.f,0.f}, a1 = {0.f,0.f}, a2 = {0.f,0.f}, a3 = {0.f,0.f};

    if (slot == 0) {   // self loop once
        float4 raw = *(const float4*)(hbase + (size_t)node * 128 + laneoff);
        const __half2* h = (const __half2*)&raw;
        float2 v;
        v = __half22float2(h[0]); a0.x += v.x; a0.y += v.y;
        v = __half22float2(h[1]); a1.x += v.x; a1.y += v.y;
        v = __half22float2(h[2]); a2.x += v.x; a2.y += v.y;
        v = __half22float2(h[3]); a3.x += v.x; a3.y += v.y;
    }

    int j = g_rowptr[node];
    const int end = g_rowptr[node + 1];
    while (j < end) {
        int navail = min(32, end - j);
        int idx = (l < navail) ? g_adj[j + l] : 0;
        int steps = (navail + 3) >> 2;
        #pragma unroll 4
        for (int k = 0; k < steps; k++) {
            int nb = (k << 2) + slot;
            int s = __shfl_sync(0xFFFFFFFFu, idx, nb & 31);
            if (nb < navail) {
                float4 raw = *(const float4*)(hbase + (size_t)s * 128 + laneoff);
                const __half2* h = (const __half2*)&raw;
                float2 v;
                v = __half22float2(h[0]); a0.x += v.x; a0.y += v.y;
                v = __half22float2(h[1]); a1.x += v.x; a1.y += v.y;
                v = __half22float2(h[2]); a2.x += v.x; a2.y += v.y;
                v = __half22float2(h[3]); a3.x += v.x; a3.y += v.y;
            }
        }
        j += navail;
    }

    #pragma unroll
    for (int d = 8; d <= 16; d <<= 1) {
        a0.x += __shfl_xor_sync(0xFFFFFFFFu, a0.x, d);
        a0.y += __shfl_xor_sync(0xFFFFFFFFu, a0.y, d);
        a1.x += __shfl_xor_sync(0xFFFFFFFFu, a1.x, d);
        a1.y += __shfl_xor_sync(0xFFFFFFFFu, a1.y, d);
        a2.x += __shfl_xor_sync(0xFFFFFFFFu, a2.x, d);
        a2.y += __shfl_xor_sync(0xFFFFFFFFu, a2.y, d);
        a3.x += __shfl_xor_sync(0xFFFFFFFFu, a3.x, d);
        a3.y += __shfl_xor_sync(0xFFFFFFFFu, a3.y, d);
    }

    if (slot == 0) {   // lanes 0..7 write the 256B row
        float4* out = (float4*)((char*)g_agg4 + (size_t)node * 256 + chunk * 32);
        out[0] = make_float4(a0.x, a0.y, a1.x, a1.y);
        out[1] = make_float4(a2.x, a2.y, a3.x, a3.y);
    }
}

// ---------------------------------------------------------------------------
// 7) transform2: t = relu(dinv*agg1 + b1); hs = half((t @ W2) * dinv)
//    [f32x2 packed FMA; t staged as dup pairs]
// ---------------------------------------------------------------------------
__global__ void transform2_kernel(const float* __restrict__ W2,
                                  const float* __restrict__ b1,
                                  int N) {
    __shared__ float Ws[HDIM * HDIM];                      // 16 KB
    __shared__ __align__(16) ull ts[8][4][HDIM];           // 16 KB (dup pairs)
    const int tid = threadIdx.x;

    for (int i = tid; i < HDIM * HDIM / 4; i += 256)
        ((float4*)Ws)[i] = ((const float4*)W2)[i];
    __syncthreads();

    const int w = tid >> 5, l = tid & 31;
    const int rowBase = blockIdx.x * 32 + w * 4;
    const float2 bv = ((const float2*)b1)[l];
    const float* g_agg = (const float*)g_agg4;

    #pragma unroll
    for (int r = 0; r < 4; r++) {
        int row = rowBase + r;
        if (row < N) {
            float d = g_dinv[row];
            float2 av = ((const float2*)(g_agg + (size_t)row * HDIM))[l];
            float t0 = fmaxf(fmaf(d, av.x, bv.x), 0.f);
            float t1 = fmaxf(fmaf(d, av.y, bv.y), 0.f);
            ull d0, d1;
            PACKDUP(d0, t0);
            PACKDUP(d1, t1);
            ((ulonglong2*)ts[w][r])[l] = make_ulonglong2(d0, d1);
        }
    }
    __syncwarp();

    const ull* Wv = (const ull*)Ws;                        // [k*32 + l]
    ull acc[4] = {0ULL, 0ULL, 0ULL, 0ULL};
    #pragma unroll 8
    for (int k2 = 0; k2 < HDIM / 2; k2++) {                // 2 k per iter
        ull w0 = Wv[(2 * k2)     * 32 + l];
        ull w1 = Wv[(2 * k2 + 1) * 32 + l];
        #pragma unroll
        for (int r = 0; r < 4; r++) {
            ulonglong2 xr = ((const ulonglong2*)ts[w][r])[k2];
            FFMA2(acc[r], xr.x, w0);
            FFMA2(acc[r], xr.y, w1);
        }
    }

    #pragma unroll
    for (int r = 0; r < 4; r++) {
        int row = rowBase + r;
        if (row < N) {
            float d = g_dinv[row];
            float ax, ay;
            UNPACK2(ax, ay, acc[r]);
            g_hsh[(size_t)row * 32 + l] = __floats2half2_rn(ax * d, ay * d);
        }
    }
}

// ---------------------------------------------------------------------------
// 8) final: out[i] = relu(dinv*agg2 + b2) @ Wlin + blin   (warp per row)
// ---------------------------------------------------------------------------
__global__ void final_kernel(const float* __restrict__ b2,
                             const float* __restrict__ Wlin,
                             const float* __restrict__ blin,
                             float* __restrict__ out, int N) {
    int warpG = (blockIdx.x * blockDim.x + threadIdx.x) >> 5;
    int l = threadIdx.x & 31;
    if (warpG >= N) return;
    int row = warpG;
    const float* g_agg = (const float*)g_agg4;
    float d = g_dinv[row];
    float2 av = ((const float2*)(g_agg + (size_t)row * HDIM))[l];
    float2 bv = ((const float2*)b2)[l];
    float2 wv = ((const float2*)Wlin)[l];
    float h0 = fmaxf(fmaf(d, av.x, bv.x), 0.f);
    float h1 = fmaxf(fmaf(d, av.y, bv.y), 0.f);
    float s = h0 * wv.x + h1 * wv.y;
    #pragma unroll
    for (int off = 16; off > 0; off >>= 1)
        s += __shfl_xor_sync(0xFFFFFFFFu, s, off);
    if (l == 0) out[row] = s + blin[0];
}

// ---------------------------------------------------------------------------
extern "C" void kernel_launch(void* const* d_in, const int* in_sizes, int n_in,
                              void* d_out, int out_size) {
    const float* x    = (const float*)d_in[0];
    const void*  ei   = d_in[1];
    const float* W1   = (const float*)d_in[2];
    const float* b1   = (const float*)d_in[3];
    const float* W2   = (const float*)d_in[4];
    const float* b2   = (const float*)d_in[5];
    const float* Wlin = (const float*)d_in[6];
    const float* blin = (const float*)d_in[7];
    float*       out  = (float*)d_out;

    const int N = in_sizes[0] / FIN;
    const int E = in_sizes[1] / 2;

    const int nb  = (N + SCAN_B - 1) / SCAN_B;       // scan blocks (all resident)
    const int eb2 = ((E + 1) / 2 + 255) / 256;       // 2 edges per thread
    const int tb  = (N + 31) / 32;                   // 32 rows per block
    const int ab  = (N * 32 + 255) / 256;            // warp per node
    const int fb  = (N + 7) / 8;

    init_kernel       <<<nb, SCAN_B>>>(ei, N);
    deg_scatter_kernel<<<eb2, 256>>>(ei, E);
    scan_kernel       <<<nb, SCAN_B>>>(N, E, nb);
    fill_kernel       <<<eb2, 256>>>(ei, E);
    transform1_kernel <<<tb, 256>>>(x, W1, N);
    agg_kernel        <<<ab, 256>>>(N);
    transform2_kernel <<<tb, 256>>>(W2, b1, N);
    agg_kernel        <<<ab, 256>>>(N);
    final_kernel      <<<fb, 256>>>(b2, Wlin, blin, out, N);
}

// round 11
// speedup vs baseline: 1.1679x; 1.1679x over previous
#include <cuda_runtime.h>
#include <cuda_fp16.h>
#include <cstdint>

#define MAXN 100000
#define MAXE 3200000
#define FIN  128
#define HDIM 64
#define KH   64          // k-half size for the fused transform
#define SCAN_B 256

// Scratch (device globals — no cudaMalloc allowed).
__device__ float   g_deg  [MAXN];
__device__ float   g_dinv [MAXN];
__device__ int     g_fillc[MAXN];
__device__ int     g_rowptr[MAXN + 1];
__device__ int     g_bsum [(MAXN + SCAN_B - 1) / SCAN_B + 1];
__device__ int     g_adj  [MAXE];
__device__ __half2 g_hsh [(size_t)MAXN * (HDIM / 2)];  // row-scaled messages (fp16)
__device__ float4  g_agg4[(size_t)MAXN * (HDIM / 4)];  // aggregation result (fp32)
__device__ int     g_is64;                             // edge-index dtype flag
__device__ int     g_scanctr;                          // grid barrier counter

// ---------------------------------------------------------------------------
// 1) init + dtype probe. int64 data => first 64 words all in [0, MAXN)
// ---------------------------------------------------------------------------
__global__ void init_kernel(const void* __restrict__ ei, int N) {
    int i = blockIdx.x * blockDim.x + threadIdx.x;
    if (i < N) g_deg[i] = 1.0f;
    if (i == 0) {
        g_scanctr = 0;                       // reset grid barrier every replay
        const long long* p = (const long long*)ei;
        int is64 = 1;
        #pragma unroll 1
        for (int k = 0; k < 64; k++) {
            long long v = p[k];
            if (v < 0 || v >= MAXN) { is64 = 0; break; }
        }
        g_is64 = is64;
    }
}

// ---------------------------------------------------------------------------
// 2) degree histogram over dst (2 edges/thread, vector index loads)
// ---------------------------------------------------------------------------
__global__ void deg_scatter_kernel(const void* __restrict__ ei, int E) {
    int t = blockIdx.x * blockDim.x + threadIdx.x;
    int e = 2 * t;
    if (e >= E) return;
    bool two = (e + 1 < E);
    int d0, d1 = 0;
    if (g_is64) {
        const long long* p = (const long long*)ei + E;
        if (two && ((E & 1) == 0)) {
            longlong2 dv = ((const longlong2*)p)[t];
            d0 = (int)dv.x; d1 = (int)dv.y;
        } else {
            d0 = (int)p[e];
            if (two) d1 = (int)p[e + 1];
        }
    } else {
        const int* p = (const int*)ei + E;
        if (two && ((E & 1) == 0)) {
            int2 dv = ((const int2*)p)[t];
            d0 = dv.x; d1 = dv.y;
        } else {
            d0 = p[e];
            if (two) d1 = p[e + 1];
        }
    }
    atomicAdd(&g_deg[d0], 1.0f);
    if (two) atomicAdd(&g_deg[d1], 1.0f);
}

// ---------------------------------------------------------------------------
// 3) single-kernel scan: local scan -> grid barrier (all 391 blocks resident)
//    -> cross-block prefix -> rowptr/fillc/dinv
// ---------------------------------------------------------------------------
__global__ void scan_kernel(int N, int E, int nblocks) {
    __shared__ int s[SCAN_B];
    __shared__ int blockPrefix;
    const int tid = threadIdx.x;
    const int i = blockIdx.x * SCAN_B + tid;

    float degv = (i < N) ? g_deg[i] : 1.0f;
    if (i < N) g_dinv[i] = rsqrtf(degv);
    int v = (i < N) ? (int)degv - 1 : 0;         // edge count into node i

    s[tid] = v;
    __syncthreads();
    #pragma unroll
    for (int off = 1; off < SCAN_B; off <<= 1) {
        int t = (tid >= off) ? s[tid - off] : 0;
        __syncthreads();
        s[tid] += t;
        __syncthreads();
    }
    const int incl = s[tid];                      // inclusive local scan
    if (tid == SCAN_B - 1) g_bsum[blockIdx.x] = incl;
    __threadfence();
    __syncthreads();

    // grid barrier (arrive-and-spin; all blocks co-resident)
    if (tid == 0) {
        atomicAdd(&g_scanctr, 1);
        while (atomicAdd(&g_scanctr, 0) < nblocks) { }
    }
    __syncthreads();
    __threadfence();

    // prefix of block sums before this block
    int p = 0;
    for (int b = tid; b < blockIdx.x; b += SCAN_B) p += g_bsum[b];
    __syncthreads();           // s[] reuse
    s[tid] = p;
    __syncthreads();
    #pragma unroll
    for (int off = SCAN_B / 2; off > 0; off >>= 1) {
        if (tid < off) s[tid] += s[tid + off];
        __syncthreads();
    }
    if (tid == 0) blockPrefix = s[0];
    __syncthreads();

    if (i < N) {
        int rp = blockPrefix + incl - v;          // exclusive global prefix
        g_rowptr[i] = rp;
        g_fillc[i]  = rp;
    }
    if (i == 0) g_rowptr[N] = E;
}

// ---------------------------------------------------------------------------
// 4) FUSED transform1 + fill, 24KB smem (k-halved W/x staging -> ~9 blocks/SM
//    co-resident, so fill's atomic latency hides inside transform compute):
//    blocks [0, tb)        : hs = half((x @ W1) * dinv[row])
//    blocks [tb, tb + eb2) : CSR fill (2 edges/thread)
// ---------------------------------------------------------------------------
__global__ void t1_fill_kernel(const float* __restrict__ x,
                               const float* __restrict__ W1,
                               const void* __restrict__ ei,
                               int N, int E, int tb) {
    __shared__ float Ws[KH * HDIM];           // 16 KB (one k-half of W1)
    __shared__ float xs[8][4][KH];            //  8 KB
    const int tid = threadIdx.x;

    if (blockIdx.x < tb) {
        // ---- transform1 role (two k-halves) ----
        const int w = tid >> 5, l = tid & 31;
        const int rowBase = blockIdx.x * 32 + w * 4;

        float2 acc[4] = {{0.f,0.f},{0.f,0.f},{0.f,0.f},{0.f,0.f}};

        #pragma unroll
        for (int half = 0; half < 2; half++) {
            const int kbase = half * KH;
            __syncthreads();                  // protect Ws from previous half
            for (int i = tid; i < KH * HDIM / 4; i += 256)
                ((float4*)Ws)[i] = ((const float4*)(W1 + kbase * HDIM))[i];
            #pragma unroll
            for (int r = 0; r < 4; r++) {
                int row = rowBase + r;
                if (row < N)
                    ((float2*)xs[w][r])[l] =
                        ((const float2*)(x + (size_t)row * FIN + kbase))[l];
            }
            __syncthreads();

            const float2* Ws2 = (const float2*)Ws;
            #pragma unroll 8
            for (int k = 0; k < KH; k++) {
                float2 wv = Ws2[k * 32 + l];  // cols (2l, 2l+1)
                #pragma unroll
                for (int r = 0; r < 4; r++) {
                    float xv = xs[w][r][k];
                    acc[r].x = fmaf(xv, wv.x, acc[r].x);
                    acc[r].y = fmaf(xv, wv.y, acc[r].y);
                }
            }
        }

        #pragma unroll
        for (int r = 0; r < 4; r++) {
            int row = rowBase + r;
            if (row < N) {
                float d = g_dinv[row];
                g_hsh[(size_t)row * 32 + l] =
                    __floats2half2_rn(acc[r].x * d, acc[r].y * d);
            }
        }
    } else {
        // ---- fill role ----
        int t = (blockIdx.x - tb) * blockDim.x + tid;
        int e = 2 * t;
        if (e >= E) return;
        bool two = (e + 1 < E);
        int s0, s1 = 0, d0, d1 = 0;
        if (g_is64) {
            const long long* p = (const long long*)ei;
            if (two && ((E & 1) == 0)) {
                longlong2 sv = ((const longlong2*)p)[t];
                longlong2 dv = ((const longlong2*)(p + E))[t];
                s0 = (int)sv.x; s1 = (int)sv.y; d0 = (int)dv.x; d1 = (int)dv.y;
            } else {
                s0 = (int)p[e]; d0 = (int)p[E + e];
                if (two) { s1 = (int)p[e + 1]; d1 = (int)p[E + e + 1]; }
            }
        } else {
            const int* p = (const int*)ei;
            if (two && ((E & 1) == 0)) {
                int2 sv = ((const int2*)p)[t];
                int2 dv = ((const int2*)(p + E))[t];
                s0 = sv.x; s1 = sv.y; d0 = dv.x; d1 = dv.y;
            } else {
                s0 = p[e]; d0 = p[E + e];
                if (two) { s1 = p[e + 1]; d1 = p[E + e + 1]; }
            }
        }
        int pos0 = atomicAdd(&g_fillc[d0], 1);
        g_adj[pos0] = s0;
        if (two) {
            int pos1 = atomicAdd(&g_fillc[d1], 1);
            g_adj[pos1] = s1;
        }
    }
}

// ---------------------------------------------------------------------------
// 5) aggregation (gather): agg[i] = hs[i] + sum_{src in adj(i)} hs[src]
//    warp per node; lane = (slot 0..3, chunk 0..7); 4 neighbors per step.
// ---------------------------------------------------------------------------
__global__ void agg_kernel(int N) {
    int node = (blockIdx.x * blockDim.x + threadIdx.x) >> 5;
    if (node >= N) return;
    const int l     = threadIdx.x & 31;
    const int slot  = l >> 3;
    const int chunk = l & 7;
    const char* hbase = (const char*)g_hsh;
    const unsigned laneoff = chunk * 16;

    float2 a0 = {0.f,0.f}, a1 = {0.f,0.f}, a2 = {0.f,0.f}, a3 = {0.f,0.f};

    if (slot == 0) {   // self loop once
        float4 raw = *(const float4*)(hbase + (size_t)node * 128 + laneoff);
        const __half2* h = (const __half2*)&raw;
        float2 v;
        v = __half22float2(h[0]); a0.x += v.x; a0.y += v.y;
        v = __half22float2(h[1]); a1.x += v.x; a1.y += v.y;
        v = __half22float2(h[2]); a2.x += v.x; a2.y += v.y;
        v = __half22float2(h[3]); a3.x += v.x; a3.y += v.y;
    }

    int j = g_rowptr[node];
    const int end = g_rowptr[node + 1];
    while (j < end) {
        int navail = min(32, end - j);
        int idx = (l < navail) ? g_adj[j + l] : 0;
        int steps = (navail + 3) >> 2;
        #pragma unroll 4
        for (int k = 0; k < steps; k++) {
            int nb = (k << 2) + slot;
            int s = __shfl_sync(0xFFFFFFFFu, idx, nb & 31);
            if (nb < navail) {
                float4 raw = *(const float4*)(hbase + (size_t)s * 128 + laneoff);
                const __half2* h = (const __half2*)&raw;
                float2 v;
                v = __half22float2(h[0]); a0.x += v.x; a0.y += v.y;
                v = __half22float2(h[1]); a1.x += v.x; a1.y += v.y;
                v = __half22float2(h[2]); a2.x += v.x; a2.y += v.y;
                v = __half22float2(h[3]); a3.x += v.x; a3.y += v.y;
            }
        }
        j += navail;
    }

    #pragma unroll
    for (int d = 8; d <= 16; d <<= 1) {
        a0.x += __shfl_xor_sync(0xFFFFFFFFu, a0.x, d);
        a0.y += __shfl_xor_sync(0xFFFFFFFFu, a0.y, d);
        a1.x += __shfl_xor_sync(0xFFFFFFFFu, a1.x, d);
        a1.y += __shfl_xor_sync(0xFFFFFFFFu, a1.y, d);
        a2.x += __shfl_xor_sync(0xFFFFFFFFu, a2.x, d);
        a2.y += __shfl_xor_sync(0xFFFFFFFFu, a2.y, d);
        a3.x += __shfl_xor_sync(0xFFFFFFFFu, a3.x, d);
        a3.y += __shfl_xor_sync(0xFFFFFFFFu, a3.y, d);
    }

    if (slot == 0) {   // lanes 0..7 write the 256B row
        float4* out = (float4*)((char*)g_agg4 + (size_t)node * 256 + chunk * 32);
        out[0] = make_float4(a0.x, a0.y, a1.x, a1.y);
        out[1] = make_float4(a2.x, a2.y, a3.x, a3.y);
    }
}

// ---------------------------------------------------------------------------
// 6) transform2: t = relu(dinv*agg1 + b1); hs = half((t @ W2) * dinv)
// ---------------------------------------------------------------------------
__global__ void transform2_kernel(const float* __restrict__ W2,
                                  const float* __restrict__ b1,
                                  int N) {
    __shared__ float Ws[HDIM * HDIM];         // 16 KB
    __shared__ float ts[8][4][HDIM];          // 8 KB
    const int tid = threadIdx.x;

    for (int i = tid; i < HDIM * HDIM / 4; i += 256)
        ((float4*)Ws)[i] = ((const float4*)W2)[i];
    __syncthreads();

    const int w = tid >> 5, l = tid & 31;
    const int rowBase = blockIdx.x * 32 + w * 4;
    const float2 bv = ((const float2*)b1)[l];
    const float* g_agg = (const float*)g_agg4;

    #pragma unroll
    for (int r = 0; r < 4; r++) {
        int row = rowBase + r;
        if (row < N) {
            float d = g_dinv[row];
            float2 av = ((const float2*)(g_agg + (size_t)row * HDIM))[l];
            float2 tv;
            tv.x = fmaxf(fmaf(d, av.x, bv.x), 0.f);
            tv.y = fmaxf(fmaf(d, av.y, bv.y), 0.f);
            ((float2*)ts[w][r])[l] = tv;
        }
    }
    __syncwarp();

    float2 acc[4] = {{0.f,0.f},{0.f,0.f},{0.f,0.f},{0.f,0.f}};
    const float2* Ws2 = (const float2*)Ws;
    #pragma unroll 8
    for (int k = 0; k < HDIM; k++) {
        float2 wv = Ws2[k * 32 + l];
        #pragma unroll
        for (int r = 0; r < 4; r++) {
            float tv = ts[w][r][k];
            acc[r].x = fmaf(tv, wv.x, acc[r].x);
            acc[r].y = fmaf(tv, wv.y, acc[r].y);
        }
    }

    #pragma unroll
    for (int r = 0; r < 4; r++) {
        int row = rowBase + r;
        if (row < N) {
            float d = g_dinv[row];
            g_hsh[(size_t)row * 32 + l] =
                __floats2half2_rn(acc[r].x * d, acc[r].y * d);
        }
    }
}

// ---------------------------------------------------------------------------
// 7) final: out[i] = relu(dinv*agg2 + b2) @ Wlin + blin   (warp per row)
// ---------------------------------------------------------------------------
__global__ void final_kernel(const float* __restrict__ b2,
                             const float* __restrict__ Wlin,
                             const float* __restrict__ blin,
                             float* __restrict__ out, int N) {
    int warpG = (blockIdx.x * blockDim.x + threadIdx.x) >> 5;
    int l = threadIdx.x & 31;
    if (warpG >= N) return;
    int row = warpG;
    const float* g_agg = (const float*)g_agg4;
    float d = g_dinv[row];
    float2 av = ((const float2*)(g_agg + (size_t)row * HDIM))[l];
    float2 bv = ((const float2*)b2)[l];
    float2 wv = ((const float2*)Wlin)[l];
    float h0 = fmaxf(fmaf(d, av.x, bv.x), 0.f);
    float h1 = fmaxf(fmaf(d, av.y, bv.y), 0.f);
    float s = h0 * wv.x + h1 * wv.y;
    #pragma unroll
    for (int off = 16; off > 0; off >>= 1)
        s += __shfl_xor_sync(0xFFFFFFFFu, s, off);
    if (l == 0) out[row] = s + blin[0];
}

// ---------------------------------------------------------------------------
extern "C" void kernel_launch(void* const* d_in, const int* in_sizes, int n_in,
                              void* d_out, int out_size) {
    const float* x    = (const float*)d_in[0];
    const void*  ei   = d_in[1];
    const float* W1   = (const float*)d_in[2];
    const float* b1   = (const float*)d_in[3];
    const float* W2   = (const float*)d_in[4];
    const float* b2   = (const float*)d_in[5];
    const float* Wlin = (const float*)d_in[6];
    const float* blin = (const float*)d_in[7];
    float*       out  = (float*)d_out;

    const int N = in_sizes[0] / FIN;
    const int E = in_sizes[1] / 2;

    const int nb  = (N + SCAN_B - 1) / SCAN_B;       // scan blocks (all resident)
    const int eb2 = ((E + 1) / 2 + 255) / 256;       // 2 edges per thread
    const int tb  = (N + 31) / 32;                   // 32 rows per block
    const int ab  = (N * 32 + 255) / 256;            // warp per node
    const int fb  = (N + 7) / 8;

    init_kernel       <<<nb, SCAN_B>>>(ei, N);
    deg_scatter_kernel<<<eb2, 256>>>(ei, E);
    scan_kernel       <<<nb, SCAN_B>>>(N, E, nb);
    t1_fill_kernel    <<<tb + eb2, 256>>>(x, W1, ei, N, E, tb);
    agg_kernel        <<<ab, 256>>>(N);
    transform2_kernel <<<tb, 256>>>(W2, b1, N);
    agg_kernel        <<<ab, 256>>>(N);
    final_kernel      <<<fb, 256>>>(b2, Wlin, blin, out, N);
}

// round 12
// speedup vs baseline: 1.1825x; 1.0124x over previous
#include <cuda_runtime.h>
#include <cuda_fp16.h>
#include <cstdint>

#define MAXN 100000
#define MAXE 3200000
#define FIN  128
#define HDIM 64
#define KH   64          // k-half size for the fused transform
#define SCAN_B 256

// Scratch (device globals — no cudaMalloc allowed).
__device__ float   g_deg  [MAXN];
__device__ float   g_dinv [MAXN];
__device__ int     g_fillc[MAXN];
__device__ int     g_rowptr[MAXN + 1];
__device__ int     g_bsum [(MAXN + SCAN_B - 1) / SCAN_B + 1];
__device__ int     g_adj  [MAXE];
__device__ __half2 g_hsh [(size_t)MAXN * (HDIM / 2)];  // row-scaled messages (fp16)
__device__ float4  g_agg4[(size_t)MAXN * (HDIM / 4)];  // aggregation result (fp32)
__device__ int     g_is64;                             // edge-index dtype flag
__device__ int     g_scanctr;                          // grid barrier counter

// ---------------------------------------------------------------------------
// 1) init + dtype probe. int64 data => first 64 words all in [0, MAXN)
// ---------------------------------------------------------------------------
__global__ void init_kernel(const void* __restrict__ ei, int N) {
    int i = blockIdx.x * blockDim.x + threadIdx.x;
    if (i < N) g_deg[i] = 1.0f;
    if (i == 0) {
        g_scanctr = 0;                       // reset grid barrier every replay
        const long long* p = (const long long*)ei;
        int is64 = 1;
        #pragma unroll 1
        for (int k = 0; k < 64; k++) {
            long long v = p[k];
            if (v < 0 || v >= MAXN) { is64 = 0; break; }
        }
        g_is64 = is64;
    }
}

// ---------------------------------------------------------------------------
// 2) degree histogram over dst (2 edges/thread, vector index loads)
// ---------------------------------------------------------------------------
__global__ void deg_scatter_kernel(const void* __restrict__ ei, int E) {
    int t = blockIdx.x * blockDim.x + threadIdx.x;
    int e = 2 * t;
    if (e >= E) return;
    bool two = (e + 1 < E);
    int d0, d1 = 0;
    if (g_is64) {
        const long long* p = (const long long*)ei + E;
        if (two && ((E & 1) == 0)) {
            longlong2 dv = ((const longlong2*)p)[t];
            d0 = (int)dv.x; d1 = (int)dv.y;
        } else {
            d0 = (int)p[e];
            if (two) d1 = (int)p[e + 1];
        }
    } else {
        const int* p = (const int*)ei + E;
        if (two && ((E & 1) == 0)) {
            int2 dv = ((const int2*)p)[t];
            d0 = dv.x; d1 = dv.y;
        } else {
            d0 = p[e];
            if (two) d1 = p[e + 1];
        }
    }
    atomicAdd(&g_deg[d0], 1.0f);
    if (two) atomicAdd(&g_deg[d1], 1.0f);
}

// ---------------------------------------------------------------------------
// 3) single-kernel scan: local scan -> grid barrier (all 391 blocks resident)
//    -> cross-block prefix -> rowptr/fillc/dinv
// ---------------------------------------------------------------------------
__global__ void scan_kernel(int N, int E, int nblocks) {
    __shared__ int s[SCAN_B];
    __shared__ int blockPrefix;
    const int tid = threadIdx.x;
    const int i = blockIdx.x * SCAN_B + tid;

    float degv = (i < N) ? g_deg[i] : 1.0f;
    if (i < N) g_dinv[i] = rsqrtf(degv);
    int v = (i < N) ? (int)degv - 1 : 0;         // edge count into node i

    s[tid] = v;
    __syncthreads();
    #pragma unroll
    for (int off = 1; off < SCAN_B; off <<= 1) {
        int t = (tid >= off) ? s[tid - off] : 0;
        __syncthreads();
        s[tid] += t;
        __syncthreads();
    }
    const int incl = s[tid];                      // inclusive local scan
    if (tid == SCAN_B - 1) g_bsum[blockIdx.x] = incl;
    __threadfence();
    __syncthreads();

    // grid barrier (arrive-and-spin; all blocks co-resident)
    if (tid == 0) {
        atomicAdd(&g_scanctr, 1);
        while (atomicAdd(&g_scanctr, 0) < nblocks) { }
    }
    __syncthreads();
    __threadfence();

    // prefix of block sums before this block
    int p = 0;
    for (int b = tid; b < blockIdx.x; b += SCAN_B) p += g_bsum[b];
    __syncthreads();           // s[] reuse
    s[tid] = p;
    __syncthreads();
    #pragma unroll
    for (int off = SCAN_B / 2; off > 0; off >>= 1) {
        if (tid < off) s[tid] += s[tid + off];
        __syncthreads();
    }
    if (tid == 0) blockPrefix = s[0];
    __syncthreads();

    if (i < N) {
        int rp = blockPrefix + incl - v;          // exclusive global prefix
        g_rowptr[i] = rp;
        g_fillc[i]  = rp;
    }
    if (i == 0) g_rowptr[N] = E;
}

// ---------------------------------------------------------------------------
// 4) FUSED transform1 + fill, 24KB smem, proportionally interleaved roles so
//    every scheduling wave mixes ~1/3 transform with ~2/3 fill blocks:
//    transform: hs = half((x @ W1) * dinv[row]);  fill: CSR adj fill.
// ---------------------------------------------------------------------------
__global__ void t1_fill_kernel(const float* __restrict__ x,
                               const float* __restrict__ W1,
                               const void* __restrict__ ei,
                               int N, int E, int tb, int total) {
    __shared__ float Ws[KH * HDIM];                        // 16 KB
    __shared__ __align__(16) float xs[8][4][KH];           //  8 KB
    const int tid = threadIdx.x;
    const int bid = blockIdx.x;

    // proportional interleave: block is 'transform' iff floor(bid*T/total)
    // increments at this bid; exactly tb transform blocks overall.
    const long long c = ((long long)bid * tb) / total;
    const bool isT = (((long long)(bid + 1) * tb) / total) > c;

    if (isT) {
        // ---- transform1 role (two k-halves) ----
        const int w = tid >> 5, l = tid & 31;
        const int rowBase = (int)c * 32 + w * 4;

        float2 acc[4] = {{0.f,0.f},{0.f,0.f},{0.f,0.f},{0.f,0.f}};

        #pragma unroll
        for (int half = 0; half < 2; half++) {
            const int kbase = half * KH;
            __syncthreads();                  // protect Ws from previous half
            for (int i = tid; i < KH * HDIM / 4; i += 256)
                ((float4*)Ws)[i] = ((const float4*)(W1 + kbase * HDIM))[i];
            #pragma unroll
            for (int r = 0; r < 4; r++) {
                int row = rowBase + r;
                if (row < N)
                    ((float2*)xs[w][r])[l] =
                        ((const float2*)(x + (size_t)row * FIN + kbase))[l];
            }
            __syncthreads();

            const float2* Ws2 = (const float2*)Ws;
            #pragma unroll 4
            for (int k4 = 0; k4 < KH / 4; k4++) {
                // 4 k's per xs load: broadcast LDS.128 per row
                float4 xv0 = ((const float4*)xs[w][0])[k4];
                float4 xv1 = ((const float4*)xs[w][1])[k4];
                float4 xv2 = ((const float4*)xs[w][2])[k4];
                float4 xv3 = ((const float4*)xs[w][3])[k4];
                #pragma unroll
                for (int kk = 0; kk < 4; kk++) {
                    float2 wv = Ws2[(k4 * 4 + kk) * 32 + l];
                    float x0 = (&xv0.x)[kk], x1 = (&xv1.x)[kk];
                    float x2 = (&xv2.x)[kk], x3 = (&xv3.x)[kk];
                    acc[0].x = fmaf(x0, wv.x, acc[0].x);
                    acc[0].y = fmaf(x0, wv.y, acc[0].y);
                    acc[1].x = fmaf(x1, wv.x, acc[1].x);
                    acc[1].y = fmaf(x1, wv.y, acc[1].y);
                    acc[2].x = fmaf(x2, wv.x, acc[2].x);
                    acc[2].y = fmaf(x2, wv.y, acc[2].y);
                    acc[3].x = fmaf(x3, wv.x, acc[3].x);
                    acc[3].y = fmaf(x3, wv.y, acc[3].y);
                }
            }
        }

        #pragma unroll
        for (int r = 0; r < 4; r++) {
            int row = rowBase + r;
            if (row < N) {
                float d = g_dinv[row];
                g_hsh[(size_t)row * 32 + l] =
                    __floats2half2_rn(acc[r].x * d, acc[r].y * d);
            }
        }
    } else {
        // ---- fill role ----
        int fIdx = bid - (int)c;                  // fill block index
        int t = fIdx * blockDim.x + tid;
        int e = 2 * t;
        if (e >= E) return;
        bool two = (e + 1 < E);
        int s0, s1 = 0, d0, d1 = 0;
        if (g_is64) {
            const long long* p = (const long long*)ei;
            if (two && ((E & 1) == 0)) {
                longlong2 sv = ((const longlong2*)p)[t];
                longlong2 dv = ((const longlong2*)(p + E))[t];
                s0 = (int)sv.x; s1 = (int)sv.y; d0 = (int)dv.x; d1 = (int)dv.y;
            } else {
                s0 = (int)p[e]; d0 = (int)p[E + e];
                if (two) { s1 = (int)p[e + 1]; d1 = (int)p[E + e + 1]; }
            }
        } else {
            const int* p = (const int*)ei;
            if (two && ((E & 1) == 0)) {
                int2 sv = ((const int2*)p)[t];
                int2 dv = ((const int2*)(p + E))[t];
                s0 = sv.x; s1 = sv.y; d0 = dv.x; d1 = dv.y;
            } else {
                s0 = p[e]; d0 = p[E + e];
                if (two) { s1 = p[e + 1]; d1 = p[E + e + 1]; }
            }
        }
        int pos0 = atomicAdd(&g_fillc[d0], 1);
        g_adj[pos0] = s0;
        if (two) {
            int pos1 = atomicAdd(&g_fillc[d1], 1);
            g_adj[pos1] = s1;
        }
    }
}

// ---------------------------------------------------------------------------
// 5) aggregation (gather): agg[i] = hs[i] + sum_{src in adj(i)} hs[src]
//    warp per node; lane = (slot 0..3, chunk 0..7); 4 neighbors per step.
// ---------------------------------------------------------------------------
__global__ void agg_kernel(int N) {
    int node = (blockIdx.x * blockDim.x + threadIdx.x) >> 5;
    if (node >= N) return;
    const int l     = threadIdx.x & 31;
    const int slot  = l >> 3;
    const int chunk = l & 7;
    const char* hbase = (const char*)g_hsh;
    const unsigned laneoff = chunk * 16;

    float2 a0 = {0.f,0.f}, a1 = {0.f,0.f}, a2 = {0.f,0.f}, a3 = {0.f,0.f};

    if (slot == 0) {   // self loop once
        float4 raw = *(const float4*)(hbase + (size_t)node * 128 + laneoff);
        const __half2* h = (const __half2*)&raw;
        float2 v;
        v = __half22float2(h[0]); a0.x += v.x; a0.y += v.y;
        v = __half22float2(h[1]); a1.x += v.x; a1.y += v.y;
        v = __half22float2(h[2]); a2.x += v.x; a2.y += v.y;
        v = __half22float2(h[3]); a3.x += v.x; a3.y += v.y;
    }

    int j = g_rowptr[node];
    const int end = g_rowptr[node + 1];
    while (j < end) {
        int navail = min(32, end - j);
        int idx = (l < navail) ? g_adj[j + l] : 0;
        int steps = (navail + 3) >> 2;
        #pragma unroll 4
        for (int k = 0; k < steps; k++) {
            int nb = (k << 2) + slot;
            int s = __shfl_sync(0xFFFFFFFFu, idx, nb & 31);
            if (nb < navail) {
                float4 raw = *(const float4*)(hbase + (size_t)s * 128 + laneoff);
                const __half2* h = (const __half2*)&raw;
                float2 v;
                v = __half22float2(h[0]); a0.x += v.x; a0.y += v.y;
                v = __half22float2(h[1]); a1.x += v.x; a1.y += v.y;
                v = __half22float2(h[2]); a2.x += v.x; a2.y += v.y;
                v = __half22float2(h[3]); a3.x += v.x; a3.y += v.y;
            }
        }
        j += navail;
    }

    #pragma unroll
    for (int d = 8; d <= 16; d <<= 1) {
        a0.x += __shfl_xor_sync(0xFFFFFFFFu, a0.x, d);
        a0.y += __shfl_xor_sync(0xFFFFFFFFu, a0.y, d);
        a1.x += __shfl_xor_sync(0xFFFFFFFFu, a1.x, d);
        a1.y += __shfl_xor_sync(0xFFFFFFFFu, a1.y, d);
        a2.x += __shfl_xor_sync(0xFFFFFFFFu, a2.x, d);
        a2.y += __shfl_xor_sync(0xFFFFFFFFu, a2.y, d);
        a3.x += __shfl_xor_sync(0xFFFFFFFFu, a3.x, d);
        a3.y += __shfl_xor_sync(0xFFFFFFFFu, a3.y, d);
    }

    if (slot == 0) {   // lanes 0..7 write the 256B row
        float4* out = (float4*)((char*)g_agg4 + (size_t)node * 256 + chunk * 32);
        out[0] = make_float4(a0.x, a0.y, a1.x, a1.y);
        out[1] = make_float4(a2.x, a2.y, a3.x, a3.y);
    }
}

// ---------------------------------------------------------------------------
// 6) transform2: t = relu(dinv*agg1 + b1); hs = half((t @ W2) * dinv)
//    (float4-vectorized ts reads: 4 k per broadcast LDS.128)
// ---------------------------------------------------------------------------
__global__ void transform2_kernel(const float* __restrict__ W2,
                                  const float* __restrict__ b1,
                                  int N) {
    __shared__ float Ws[HDIM * HDIM];                      // 16 KB
    __shared__ __align__(16) float ts[8][4][HDIM];         //  8 KB
    const int tid = threadIdx.x;

    for (int i = tid; i < HDIM * HDIM / 4; i += 256)
        ((float4*)Ws)[i] = ((const float4*)W2)[i];
    __syncthreads();

    const int w = tid >> 5, l = tid & 31;
    const int rowBase = blockIdx.x * 32 + w * 4;
    const float2 bv = ((const float2*)b1)[l];
    const float* g_agg = (const float*)g_agg4;

    #pragma unroll
    for (int r = 0; r < 4; r++) {
        int row = rowBase + r;
        if (row < N) {
            float d = g_dinv[row];
            float2 av = ((const float2*)(g_agg + (size_t)row * HDIM))[l];
            float2 tv;
            tv.x = fmaxf(fmaf(d, av.x, bv.x), 0.f);
            tv.y = fmaxf(fmaf(d, av.y, bv.y), 0.f);
            ((float2*)ts[w][r])[l] = tv;
        }
    }
    __syncwarp();

    float2 acc[4] = {{0.f,0.f},{0.f,0.f},{0.f,0.f},{0.f,0.f}};
    const float2* Ws2 = (const float2*)Ws;
    #pragma unroll 4
    for (int k4 = 0; k4 < HDIM / 4; k4++) {
        float4 xv0 = ((const float4*)ts[w][0])[k4];
        float4 xv1 = ((const float4*)ts[w][1])[k4];
        float4 xv2 = ((const float4*)ts[w][2])[k4];
        float4 xv3 = ((const float4*)ts[w][3])[k4];
        #pragma unroll
        for (int kk = 0; kk < 4; kk++) {
            float2 wv = Ws2[(k4 * 4 + kk) * 32 + l];
            float x0 = (&xv0.x)[kk], x1 = (&xv1.x)[kk];
            float x2 = (&xv2.x)[kk], x3 = (&xv3.x)[kk];
            acc[0].x = fmaf(x0, wv.x, acc[0].x);
            acc[0].y = fmaf(x0, wv.y, acc[0].y);
            acc[1].x = fmaf(x1, wv.x, acc[1].x);
            acc[1].y = fmaf(x1, wv.y, acc[1].y);
            acc[2].x = fmaf(x2, wv.x, acc[2].x);
            acc[2].y = fmaf(x2, wv.y, acc[2].y);
            acc[3].x = fmaf(x3, wv.x, acc[3].x);
            acc[3].y = fmaf(x3, wv.y, acc[3].y);
        }
    }

    #pragma unroll
    for (int r = 0; r < 4; r++) {
        int row = rowBase + r;
        if (row < N) {
            float d = g_dinv[row];
            g_hsh[(size_t)row * 32 + l] =
                __floats2half2_rn(acc[r].x * d, acc[r].y * d);
        }
    }
}

// ---------------------------------------------------------------------------
// 7) final: out[i] = relu(dinv*agg2 + b2) @ Wlin + blin   (warp per row)
// ---------------------------------------------------------------------------
__global__ void final_kernel(const float* __restrict__ b2,
                             const float* __restrict__ Wlin,
                             const float* __restrict__ blin,
                             float* __restrict__ out, int N) {
    int warpG = (blockIdx.x * blockDim.x + threadIdx.x) >> 5;
    int l = threadIdx.x & 31;
    if (warpG >= N) return;
    int row = warpG;
    const float* g_agg = (const float*)g_agg4;
    float d = g_dinv[row];
    float2 av = ((const float2*)(g_agg + (size_t)row * HDIM))[l];
    float2 bv = ((const float2*)b2)[l];
    float2 wv = ((const float2*)Wlin)[l];
    float h0 = fmaxf(fmaf(d, av.x, bv.x), 0.f);
    float h1 = fmaxf(fmaf(d, av.y, bv.y), 0.f);
    float s = h0 * wv.x + h1 * wv.y;
    #pragma unroll
    for (int off = 16; off > 0; off >>= 1)
        s += __shfl_xor_sync(0xFFFFFFFFu, s, off);
    if (l == 0) out[row] = s + blin[0];
}

// ---------------------------------------------------------------------------
extern "C" void kernel_launch(void* const* d_in, const int* in_sizes, int n_in,
                              void* d_out, int out_size) {
    const float* x    = (const float*)d_in[0];
    const void*  ei   = d_in[1];
    const float* W1   = (const float*)d_in[2];
    const float* b1   = (const float*)d_in[3];
    const float* W2   = (const float*)d_in[4];
    const float* b2   = (const float*)d_in[5];
    const float* Wlin = (const float*)d_in[6];
    const float* blin = (const float*)d_in[7];
    float*       out  = (float*)d_out;

    const int N = in_sizes[0] / FIN;
    const int E = in_sizes[1] / 2;

    const int nb  = (N + SCAN_B - 1) / SCAN_B;       // scan blocks (all resident)
    const int eb2 = ((E + 1) / 2 + 255) / 256;       // 2 edges per thread
    const int tb  = (N + 31) / 32;                   // 32 rows per block
    const int ab  = (N * 32 + 255) / 256;            // warp per node
    const int fb  = (N + 7) / 8;
    const int tot = tb + eb2;

    init_kernel       <<<nb, SCAN_B>>>(ei, N);
    deg_scatter_kernel<<<eb2, 256>>>(ei, E);
    scan_kernel       <<<nb, SCAN_B>>>(N, E, nb);
    t1_fill_kernel    <<<tot, 256>>>(x, W1, ei, N, E, tb, tot);
    agg_kernel        <<<ab, 256>>>(N);
    transform2_kernel <<<tb, 256>>>(W2, b1, N);
    agg_kernel        <<<ab, 256>>>(N);
    final_kernel      <<<fb, 256>>>(b2, Wlin, blin, out, N);
}

// round 13
// speedup vs baseline: 1.2143x; 1.0269x over previous
#include <cuda_runtime.h>
#include <cuda_fp16.h>
#include <cstdint>

#define MAXN 100000
#define MAXE 3200000
#define FIN  128
#define HDIM 64
#define SCAN_B 256

// Scratch (device globals — no cudaMalloc allowed).
__device__ float   g_deg  [MAXN];
__device__ float   g_dinv [MAXN];
__device__ int     g_fillc[MAXN];
__device__ int     g_rowptr[MAXN + 1];
__device__ int     g_bsum [(MAXN + SCAN_B - 1) / SCAN_B + 1];
__device__ int     g_adj  [MAXE];
__device__ __half2 g_hsh [(size_t)MAXN * (HDIM / 2)];  // row-scaled messages (fp16)
__device__ float4  g_agg4[(size_t)MAXN * (HDIM / 4)];  // aggregation result (fp32)
__device__ int     g_is64;                             // edge-index dtype flag
__device__ int     g_scanctr;                          // grid barrier counter

// ---------------------------------------------------------------------------
// 1) init + dtype probe. int64 data => first 64 words all in [0, MAXN)
// ---------------------------------------------------------------------------
__global__ void init_kernel(const void* __restrict__ ei, int N) {
    int i = blockIdx.x * blockDim.x + threadIdx.x;
    if (i < N) g_deg[i] = 1.0f;
    if (i == 0) {
        g_scanctr = 0;                       // reset grid barrier every replay
        const long long* p = (const long long*)ei;
        int is64 = 1;
        #pragma unroll 1
        for (int k = 0; k < 64; k++) {
            long long v = p[k];
            if (v < 0 || v >= MAXN) { is64 = 0; break; }
        }
        g_is64 = is64;
    }
}

// ---------------------------------------------------------------------------
// 2) degree histogram over dst (2 edges/thread, vector index loads)
// ---------------------------------------------------------------------------
__global__ void deg_scatter_kernel(const void* __restrict__ ei, int E) {
    int t = blockIdx.x * blockDim.x + threadIdx.x;
    int e = 2 * t;
    if (e >= E) return;
    bool two = (e + 1 < E);
    int d0, d1 = 0;
    if (g_is64) {
        const long long* p = (const long long*)ei + E;
        if (two && ((E & 1) == 0)) {
            longlong2 dv = ((const longlong2*)p)[t];
            d0 = (int)dv.x; d1 = (int)dv.y;
        } else {
            d0 = (int)p[e];
            if (two) d1 = (int)p[e + 1];
        }
    } else {
        const int* p = (const int*)ei + E;
        if (two && ((E & 1) == 0)) {
            int2 dv = ((const int2*)p)[t];
            d0 = dv.x; d1 = dv.y;
        } else {
            d0 = p[e];
            if (two) d1 = p[e + 1];
        }
    }
    atomicAdd(&g_deg[d0], 1.0f);
    if (two) atomicAdd(&g_deg[d1], 1.0f);
}

// ---------------------------------------------------------------------------
// 3) single-kernel scan: local scan -> grid barrier (all 391 blocks resident)
//    -> cross-block prefix -> rowptr/fillc/dinv
// ---------------------------------------------------------------------------
__global__ void scan_kernel(int N, int E, int nblocks) {
    __shared__ int s[SCAN_B];
    __shared__ int blockPrefix;
    const int tid = threadIdx.x;
    const int i = blockIdx.x * SCAN_B + tid;

    float degv = (i < N) ? g_deg[i] : 1.0f;
    if (i < N) g_dinv[i] = rsqrtf(degv);
    int v = (i < N) ? (int)degv - 1 : 0;         // edge count into node i

    s[tid] = v;
    __syncthreads();
    #pragma unroll
    for (int off = 1; off < SCAN_B; off <<= 1) {
        int t = (tid >= off) ? s[tid - off] : 0;
        __syncthreads();
        s[tid] += t;
        __syncthreads();
    }
    const int incl = s[tid];                      // inclusive local scan
    if (tid == SCAN_B - 1) g_bsum[blockIdx.x] = incl;
    __threadfence();
    __syncthreads();

    // grid barrier (arrive-and-spin; all blocks co-resident)
    if (tid == 0) {
        atomicAdd(&g_scanctr, 1);
        while (atomicAdd(&g_scanctr, 0) < nblocks) { }
    }
    __syncthreads();
    __threadfence();

    // prefix of block sums before this block
    int p = 0;
    for (int b = tid; b < blockIdx.x; b += SCAN_B) p += g_bsum[b];
    __syncthreads();           // s[] reuse
    s[tid] = p;
    __syncthreads();
    #pragma unroll
    for (int off = SCAN_B / 2; off > 0; off >>= 1) {
        if (tid < off) s[tid] += s[tid + off];
        __syncthreads();
    }
    if (tid == 0) blockPrefix = s[0];
    __syncthreads();

    if (i < N) {
        int rp = blockPrefix + incl - v;          // exclusive global prefix
        g_rowptr[i] = rp;
        g_fillc[i]  = rp;
    }
    if (i == 0) g_rowptr[N] = E;
}

// ---------------------------------------------------------------------------
// 4) CSR fill (0 smem -> full occupancy; latency-bound on L2 atomics)
// ---------------------------------------------------------------------------
__global__ void fill_kernel(const void* __restrict__ ei, int E) {
    int t = blockIdx.x * blockDim.x + threadIdx.x;
    int e = 2 * t;
    if (e >= E) return;
    bool two = (e + 1 < E);
    int s0, s1 = 0, d0, d1 = 0;
    if (g_is64) {
        const long long* p = (const long long*)ei;
        if (two && ((E & 1) == 0)) {
            longlong2 sv = ((const longlong2*)p)[t];
            longlong2 dv = ((const longlong2*)(p + E))[t];
            s0 = (int)sv.x; s1 = (int)sv.y; d0 = (int)dv.x; d1 = (int)dv.y;
        } else {
            s0 = (int)p[e]; d0 = (int)p[E + e];
            if (two) { s1 = (int)p[e + 1]; d1 = (int)p[E + e + 1]; }
        }
    } else {
        const int* p = (const int*)ei;
        if (two && ((E & 1) == 0)) {
            int2 sv = ((const int2*)p)[t];
            int2 dv = ((const int2*)(p + E))[t];
            s0 = sv.x; s1 = sv.y; d0 = dv.x; d1 = dv.y;
        } else {
            s0 = p[e]; d0 = p[E + e];
            if (two) { s1 = p[e + 1]; d1 = p[E + e + 1]; }
        }
    }
    int pos0 = atomicAdd(&g_fillc[d0], 1);
    g_adj[pos0] = s0;
    if (two) {
        int pos1 = atomicAdd(&g_fillc[d1], 1);
        g_adj[pos1] = s1;
    }
}

// ---------------------------------------------------------------------------
// 5) transform1 on tensor cores: hs = half((x @ W1) * dinv[row])
//    mma.sync m16n8k16 f16*f16+f32. Block = 128 thr (4 warps), 64 rows/block.
//    smem rows padded to 136 halves (272B) -> conflict-free fragment loads.
// ---------------------------------------------------------------------------
__global__ void transform1_mma_kernel(const float* __restrict__ x,
                                      const float* __restrict__ W1,
                                      int N) {
    __shared__ __half xs[64][136];     // x tile (fp16), padded
    __shared__ __half wt[64][136];     // wt[n][k] = W1[k][n] (fp16), padded
    const int tid  = threadIdx.x;
    const int w    = tid >> 5;
    const int lane = tid & 31;
    const int rowBase = blockIdx.x * 64;

    // stage W1 transposed: wt[n][k]
    for (int i = tid; i < FIN * HDIM; i += 128) {
        int k = i >> 6, n = i & 63;
        wt[n][k] = __float2half(W1[i]);
    }
    // stage x rows as fp16 (float4 -> 2x half2)
    for (int i = tid; i < 64 * (FIN / 4); i += 128) {
        int r = i >> 5;
        int c4 = (i & 31) * 4;
        int row = rowBase + r;
        if (row < N) {
            float4 v = *(const float4*)(x + (size_t)row * FIN + c4);
            *(half2*)(&xs[r][c4])     = __floats2half2_rn(v.x, v.y);
            *(half2*)(&xs[r][c4 + 2]) = __floats2half2_rn(v.z, v.w);
        } else {
            *(half2*)(&xs[r][c4])     = __floats2half2_rn(0.f, 0.f);
            *(half2*)(&xs[r][c4 + 2]) = __floats2half2_rn(0.f, 0.f);
        }
    }
    __syncthreads();

    // each warp: rows [w*16, w*16+16), all 64 cols
    const int rloc = w * 16 + (lane >> 2);        // local row of c0/c1
    const int cfrag = (lane & 3) * 2;

    float acc[8][4];
    #pragma unroll
    for (int nt = 0; nt < 8; nt++)
        #pragma unroll
        for (int j = 0; j < 4; j++) acc[nt][j] = 0.f;

    #pragma unroll
    for (int kt = 0; kt < FIN / 16; kt++) {
        const int kc = kt * 16 + cfrag;
        uint32_t a0 = *(const uint32_t*)(&xs[rloc][kc]);
        uint32_t a1 = *(const uint32_t*)(&xs[rloc + 8][kc]);
        uint32_t a2 = *(const uint32_t*)(&xs[rloc][kc + 8]);
        uint32_t a3 = *(const uint32_t*)(&xs[rloc + 8][kc + 8]);
        #pragma unroll
        for (int nt = 0; nt < 8; nt++) {
            const int nrow = nt * 8 + (lane >> 2);
            uint32_t b0 = *(const uint32_t*)(&wt[nrow][kc]);
            uint32_t b1 = *(const uint32_t*)(&wt[nrow][kc + 8]);
            asm volatile(
                "mma.sync.aligned.m16n8k16.row.col.f32.f16.f16.f32 "
                "{%0,%1,%2,%3}, {%4,%5,%6,%7}, {%8,%9}, {%0,%1,%2,%3};\n"
                : "+f"(acc[nt][0]), "+f"(acc[nt][1]),
                  "+f"(acc[nt][2]), "+f"(acc[nt][3])
                : "r"(a0), "r"(a1), "r"(a2), "r"(a3), "r"(b0), "r"(b1));
        }
    }

    // epilogue: c0/c1 -> (row0, col, col+1); c2/c3 -> (row0+8, col, col+1)
    const int row0 = rowBase + rloc;
    const int row1 = row0 + 8;
    const float d0 = (row0 < N) ? g_dinv[row0] : 0.f;
    const float d1 = (row1 < N) ? g_dinv[row1] : 0.f;
    #pragma unroll
    for (int nt = 0; nt < 8; nt++) {
        const int cp = (nt * 8 + cfrag) >> 1;     // half2 column index
        if (row0 < N)
            g_hsh[(size_t)row0 * 32 + cp] =
                __floats2half2_rn(acc[nt][0] * d0, acc[nt][1] * d0);
        if (row1 < N)
            g_hsh[(size_t)row1 * 32 + cp] =
                __floats2half2_rn(acc[nt][2] * d1, acc[nt][3] * d1);
    }
}

// ---------------------------------------------------------------------------
// 6) aggregation (gather): agg[i] = hs[i] + sum_{src in adj(i)} hs[src]
//    warp per node; lane = (slot 0..3, chunk 0..7); 4 neighbors per step.
// ---------------------------------------------------------------------------
__global__ void agg_kernel(int N) {
    int node = (blockIdx.x * blockDim.x + threadIdx.x) >> 5;
    if (node >= N) return;
    const int l     = threadIdx.x & 31;
    const int slot  = l >> 3;
    const int chunk = l & 7;
    const char* hbase = (const char*)g_hsh;
    const unsigned laneoff = chunk * 16;

    float2 a0 = {0.f,0.f}, a1 = {0.f,0.f}, a2 = {0.f,0.f}, a3 = {0.f,0.f};

    if (slot == 0) {   // self loop once
        float4 raw = *(const float4*)(hbase + (size_t)node * 128 + laneoff);
        const __half2* h = (const __half2*)&raw;
        float2 v;
        v = __half22float2(h[0]); a0.x += v.x; a0.y += v.y;
        v = __half22float2(h[1]); a1.x += v.x; a1.y += v.y;
        v = __half22float2(h[2]); a2.x += v.x; a2.y += v.y;
        v = __half22float2(h[3]); a3.x += v.x; a3.y += v.y;
    }

    int j = g_rowptr[node];
    const int end = g_rowptr[node + 1];
    while (j < end) {
        int navail = min(32, end - j);
        int idx = (l < navail) ? g_adj[j + l] : 0;
        int steps = (navail + 3) >> 2;
        #pragma unroll 4
        for (int k = 0; k < steps; k++) {
            int nb = (k << 2) + slot;
            int s = __shfl_sync(0xFFFFFFFFu, idx, nb & 31);
            if (nb < navail) {
                float4 raw = *(const float4*)(hbase + (size_t)s * 128 + laneoff);
                const __half2* h = (const __half2*)&raw;
                float2 v;
                v = __half22float2(h[0]); a0.x += v.x; a0.y += v.y;
                v = __half22float2(h[1]); a1.x += v.x; a1.y += v.y;
                v = __half22float2(h[2]); a2.x += v.x; a2.y += v.y;
                v = __half22float2(h[3]); a3.x += v.x; a3.y += v.y;
            }
        }
        j += navail;
    }

    #pragma unroll
    for (int d = 8; d <= 16; d <<= 1) {
        a0.x += __shfl_xor_sync(0xFFFFFFFFu, a0.x, d);
        a0.y += __shfl_xor_sync(0xFFFFFFFFu, a0.y, d);
        a1.x += __shfl_xor_sync(0xFFFFFFFFu, a1.x, d);
        a1.y += __shfl_xor_sync(0xFFFFFFFFu, a1.y, d);
        a2.x += __shfl_xor_sync(0xFFFFFFFFu, a2.x, d);
        a2.y += __shfl_xor_sync(0xFFFFFFFFu, a2.y, d);
        a3.x += __shfl_xor_sync(0xFFFFFFFFu, a3.x, d);
        a3.y += __shfl_xor_sync(0xFFFFFFFFu, a3.y, d);
    }

    if (slot == 0) {   // lanes 0..7 write the 256B row
        float4* out = (float4*)((char*)g_agg4 + (size_t)node * 256 + chunk * 32);
        out[0] = make_float4(a0.x, a0.y, a1.x, a1.y);
        out[1] = make_float4(a2.x, a2.y, a3.x, a3.y);
    }
}

// ---------------------------------------------------------------------------
// 7) transform2: t = relu(dinv*agg1 + b1); hs = half((t @ W2) * dinv)
//    (float4-vectorized ts reads: 4 k per broadcast LDS.128)
// ---------------------------------------------------------------------------
__global__ void transform2_kernel(const float* __restrict__ W2,
                                  const float* __restrict__ b1,
                                  int N) {
    __shared__ float Ws[HDIM * HDIM];                      // 16 KB
    __shared__ __align__(16) float ts[8][4][HDIM];         //  8 KB
    const int tid = threadIdx.x;

    for (int i = tid; i < HDIM * HDIM / 4; i += 256)
        ((float4*)Ws)[i] = ((const float4*)W2)[i];
    __syncthreads();

    const int w = tid >> 5, l = tid & 31;
    const int rowBase = blockIdx.x * 32 + w * 4;
    const float2 bv = ((const float2*)b1)[l];
    const float* g_agg = (const float*)g_agg4;

    #pragma unroll
    for (int r = 0; r < 4; r++) {
        int row = rowBase + r;
        if (row < N) {
            float d = g_dinv[row];
            float2 av = ((const float2*)(g_agg + (size_t)row * HDIM))[l];
            float2 tv;
            tv.x = fmaxf(fmaf(d, av.x, bv.x), 0.f);
            tv.y = fmaxf(fmaf(d, av.y, bv.y), 0.f);
            ((float2*)ts[w][r])[l] = tv;
        }
    }
    __syncwarp();

    float2 acc[4] = {{0.f,0.f},{0.f,0.f},{0.f,0.f},{0.f,0.f}};
    const float2* Ws2 = (const float2*)Ws;
    #pragma unroll 4
    for (int k4 = 0; k4 < HDIM / 4; k4++) {
        float4 xv0 = ((const float4*)ts[w][0])[k4];
        float4 xv1 = ((const float4*)ts[w][1])[k4];
        float4 xv2 = ((const float4*)ts[w][2])[k4];
        float4 xv3 = ((const float4*)ts[w][3])[k4];
        #pragma unroll
        for (int kk = 0; kk < 4; kk++) {
            float2 wv = Ws2[(k4 * 4 + kk) * 32 + l];
            float x0 = (&xv0.x)[kk], x1 = (&xv1.x)[kk];
            float x2 = (&xv2.x)[kk], x3 = (&xv3.x)[kk];
            acc[0].x = fmaf(x0, wv.x, acc[0].x);
            acc[0].y = fmaf(x0, wv.y, acc[0].y);
            acc[1].x = fmaf(x1, wv.x, acc[1].x);
            acc[1].y = fmaf(x1, wv.y, acc[1].y);
            acc[2].x = fmaf(x2, wv.x, acc[2].x);
            acc[2].y = fmaf(x2, wv.y, acc[2].y);
            acc[3].x = fmaf(x3, wv.x, acc[3].x);
            acc[3].y = fmaf(x3, wv.y, acc[3].y);
        }
    }

    #pragma unroll
    for (int r = 0; r < 4; r++) {
        int row = rowBase + r;
        if (row < N) {
            float d = g_dinv[row];
            g_hsh[(size_t)row * 32 + l] =
                __floats2half2_rn(acc[r].x * d, acc[r].y * d);
        }
    }
}

// ---------------------------------------------------------------------------
// 8) final: out[i] = relu(dinv*agg2 + b2) @ Wlin + blin   (warp per row)
// ---------------------------------------------------------------------------
__global__ void final_kernel(const float* __restrict__ b2,
                             const float* __restrict__ Wlin,
                             const float* __restrict__ blin,
                             float* __restrict__ out, int N) {
    int warpG = (blockIdx.x * blockDim.x + threadIdx.x) >> 5;
    int l = threadIdx.x & 31;
    if (warpG >= N) return;
    int row = warpG;
    const float* g_agg = (const float*)g_agg4;
    float d = g_dinv[row];
    float2 av = ((const float2*)(g_agg + (size_t)row * HDIM))[l];
    float2 bv = ((const float2*)b2)[l];
    float2 wv = ((const float2*)Wlin)[l];
    float h0 = fmaxf(fmaf(d, av.x, bv.x), 0.f);
    float h1 = fmaxf(fmaf(d, av.y, bv.y), 0.f);
    float s = h0 * wv.x + h1 * wv.y;
    #pragma unroll
    for (int off = 16; off > 0; off >>= 1)
        s += __shfl_xor_sync(0xFFFFFFFFu, s, off);
    if (l == 0) out[row] = s + blin[0];
}

// ---------------------------------------------------------------------------
extern "C" void kernel_launch(void* const* d_in, const int* in_sizes, int n_in,
                              void* d_out, int out_size) {
    const float* x    = (const float*)d_in[0];
    const void*  ei   = d_in[1];
    const float* W1   = (const float*)d_in[2];
    const float* b1   = (const float*)d_in[3];
    const float* W2   = (const float*)d_in[4];
    const float* b2   = (const float*)d_in[5];
    const float* Wlin = (const float*)d_in[6];
    const float* blin = (const float*)d_in[7];
    float*       out  = (float*)d_out;

    const int N = in_sizes[0] / FIN;
    const int E = in_sizes[1] / 2;

    const int nb  = (N + SCAN_B - 1) / SCAN_B;       // scan blocks (all resident)
    const int eb2 = ((E + 1) / 2 + 255) / 256;       // 2 edges per thread
    const int mb  = (N + 63) / 64;                   // mma blocks (64 rows each)
    const int tb  = (N + 31) / 32;                   // transform2 blocks
    const int ab  = (N * 32 + 255) / 256;            // warp per node
    const int fb  = (N + 7) / 8;

    init_kernel          <<<nb, SCAN_B>>>(ei, N);
    deg_scatter_kernel   <<<eb2, 256>>>(ei, E);
    scan_kernel          <<<nb, SCAN_B>>>(N, E, nb);
    fill_kernel          <<<eb2, 256>>>(ei, E);
    transform1_mma_kernel<<<mb, 128>>>(x, W1, N);
    agg_kernel           <<<ab, 256>>>(N);
    transform2_kernel    <<<tb, 256>>>(W2, b1, N);
    agg_kernel           <<<ab, 256>>>(N);
    final_kernel         <<<fb, 256>>>(b2, Wlin, blin, out, N);
}